// round 4
// baseline (speedup 1.0000x reference)
#include <cuda_runtime.h>
#include <cfloat>

// Problem constants (fixed by the dataset)
#define D        64
#define KCODES   1024
#define TM       128   // rows per block
#define TK       128   // codes per smem chunk
#define THREADS  256

// zn summation-order emulation mode (XLA:CPU guess):
//   0: sequential
//   1: 4 lanes, horizontal (S0+S2)+(S1+S3)   [XLA AddReduce shuffle-halving]
//   2: 4 lanes, horizontal (S0+S1)+(S2+S3)   [aarch64 faddp lowering]
#define ZN_MODE 1

typedef unsigned long long u64;
typedef unsigned int       u32;

// Scratch (allocation-free rule: __device__ globals)
__device__ float g_en[KCODES];        // ||e_k||^2, reference-order fp32
__device__ float g_partial[1024];     // per-block sum of min distances

struct Smem {
  float zs[D][TM];       // z tile, d-major (transposed)           32 KB
  u64   es[D][TK];       // e chunk, d-major, duplicated f32x2     64 KB
  float ens[TK];         // ||e||^2 for chunk
  u64   keys[TM];        // packed (orderable(d)<<32)|index
  float zn[TM];          // ||z_row||^2, reference-order fp32
  float red[8];          // loss warp partials
};

__device__ __forceinline__ u32 fkey(float f) {
  u32 u = __float_as_uint(f);
  return (u & 0x80000000u) ? ~u : (u | 0x80000000u);
}
__device__ __forceinline__ float funkey(u32 u) {
  u32 v = (u & 0x80000000u) ? (u & 0x7FFFFFFFu) : ~u;
  return __uint_as_float(v);
}
__device__ __forceinline__ u64 pack2(float f) {
  u64 r; u32 b = __float_as_uint(f);
  asm("mov.b64 %0, {%1, %1};" : "=l"(r) : "r"(b));
  return r;
}
__device__ __forceinline__ void ffma2(u64& acc, u64 a, u64 b) {
  asm("fma.rn.f32x2 %0, %1, %2, %0;" : "+l"(acc) : "l"(a), "l"(b));
}

// Reference-order squared-norm of 64 values at (base, stride):
// emulates XLA:CPU fp32 reduce (each mul rounds, each add rounds).
__device__ __forceinline__ float ref_sqnorm(const float* base, int stride) {
#if ZN_MODE == 0
  float s = 0.f;
  #pragma unroll
  for (int i = 0; i < D; i++) {
    float v = base[i * stride];
    s = __fadd_rn(s, __fmul_rn(v, v));
  }
  return s;
#else
  float S[4] = {0.f, 0.f, 0.f, 0.f};
  #pragma unroll
  for (int i = 0; i < D / 4; i++) {
    #pragma unroll
    for (int j = 0; j < 4; j++) {
      float v = base[(4 * i + j) * stride];
      S[j] = __fadd_rn(S[j], __fmul_rn(v, v));
    }
  }
#if ZN_MODE == 1
  return __fadd_rn(__fadd_rn(S[0], S[2]), __fadd_rn(S[1], S[3]));
#else
  return __fadd_rn(__fadd_rn(S[0], S[1]), __fadd_rn(S[2], S[3]));
#endif
#endif
}

// ---------------------------------------------------------------------------
// Kernel 0: codebook norms ||e_k||^2 (reference fp32 order)
// ---------------------------------------------------------------------------
__global__ void vq_en_kernel(const float* __restrict__ emb) {
  int k = blockIdx.x * blockDim.x + threadIdx.x;
  if (k < KCODES)
    g_en[k] = ref_sqnorm(emb + (size_t)k * D, 1);
}

// ---------------------------------------------------------------------------
// Kernel 1: scores + quantized argmin (reference numerics) + gather + loss
// ---------------------------------------------------------------------------
__global__ void __launch_bounds__(THREADS, 2)
vq_main_kernel(const float* __restrict__ z, const float* __restrict__ emb,
               float* __restrict__ out_zq, float* __restrict__ out_idx) {
  extern __shared__ __align__(16) unsigned char smem_raw[];
  Smem& s = *reinterpret_cast<Smem*>(smem_raw);
  const int t = threadIdx.x;
  const int rowBase = blockIdx.x * TM;

  for (int i = t; i < TM; i += THREADS) s.keys[i] = ~0ULL;

  // Load z tile transposed. 2 threads per row, each loads half as 8x float4.
  {
    const int r = t >> 1, h = t & 1;
    const float4* zr = (const float4*)(z + (size_t)(rowBase + r) * D + h * 32);
    #pragma unroll
    for (int i = 0; i < 8; i++) {
      float4 v = zr[i];
      int d0 = h * 32 + i * 4;
      s.zs[d0 + 0][r] = v.x; s.zs[d0 + 1][r] = v.y;
      s.zs[d0 + 2][r] = v.z; s.zs[d0 + 3][r] = v.w;
    }
  }
  __syncthreads();

  // ||z_row||^2 in the reference's exact fp32 summation order.
  // zs is [D][TM], so row r's values sit at stride TM from &zs[0][r].
  if (t < TM)
    s.zn[t] = ref_sqnorm(&s.zs[0][t], TM);
  __syncthreads();

  const int cg = t & 15;   // col group: 8 codes
  const int rg = t >> 4;   // row group: 8 rows

  float znr[8];
  #pragma unroll
  for (int i = 0; i < 8; i++) znr[i] = s.zn[rg * 8 + i];

  float minv[8];
  int   mini[8];
  #pragma unroll
  for (int i = 0; i < 8; i++) { minv[i] = FLT_MAX; mini[i] = 0; }

  for (int kc = 0; kc < KCODES; kc += TK) {
    __syncthreads();   // prior chunk's reads done before overwrite
    {
      const int r = t >> 1, h = t & 1;   // r = local code
      const float4* er = (const float4*)(emb + (size_t)(kc + r) * D + h * 32);
      #pragma unroll
      for (int i = 0; i < 8; i++) {
        float4 v = er[i];
        int d0 = h * 32 + i * 4;
        s.es[d0 + 0][r] = pack2(v.x); s.es[d0 + 1][r] = pack2(v.y);
        s.es[d0 + 2][r] = pack2(v.z); s.es[d0 + 3][r] = pack2(v.w);
      }
      if (t < TK) s.ens[t] = g_en[kc + t];
    }
    __syncthreads();

    // 8 rows x 8 cols per thread; rows packed in pairs as f32x2.
    u64 acc[4][8];
    #pragma unroll
    for (int i = 0; i < 4; i++)
      #pragma unroll
      for (int j = 0; j < 8; j++) acc[i][j] = 0ULL;

    #pragma unroll 4
    for (int d = 0; d < D; d++) {
      u64 za[4];
      #pragma unroll
      for (int i = 0; i < 4; i++)
        za[i] = *(const u64*)&s.zs[d][rg * 8 + 2 * i];
      u64 ep[8];
      #pragma unroll
      for (int m = 0; m < 4; m++) {
        ulonglong2 e2 = *(const ulonglong2*)&s.es[d][cg * 8 + 2 * m];
        ep[2 * m] = e2.x; ep[2 * m + 1] = e2.y;
      }
      #pragma unroll
      for (int i = 0; i < 4; i++)
        #pragma unroll
        for (int j = 0; j < 8; j++)
          ffma2(acc[i][j], za[i], ep[j]);
    }

    // Reference numerics: d = fl(fl(zn + en) - 2*dot). Quantized argmin,
    // strict < keeps first (lowest) index within the thread's ascending cols.
    #pragma unroll
    for (int j = 0; j < 8; j++) {
      const int col = kc + cg * 8 + j;
      const float en = s.ens[cg * 8 + j];
      #pragma unroll
      for (int i = 0; i < 4; i++) {
        u64 a = acc[i][j];
        float lo = __uint_as_float((u32)a);
        float hi = __uint_as_float((u32)(a >> 32));
        float d0 = __fsub_rn(__fadd_rn(znr[2 * i],     en), __fadd_rn(lo, lo));
        float d1 = __fsub_rn(__fadd_rn(znr[2 * i + 1], en), __fadd_rn(hi, hi));
        if (d0 < minv[2 * i])     { minv[2 * i]     = d0; mini[2 * i]     = col; }
        if (d1 < minv[2 * i + 1]) { minv[2 * i + 1] = d1; mini[2 * i + 1] = col; }
      }
    }
  }

  // cross-thread argmin: packed key min picks min d, tie -> lowest index
  #pragma unroll
  for (int i = 0; i < 8; i++) {
    u64 key = ((u64)fkey(minv[i]) << 32) | (u32)mini[i];
    atomicMin(&s.keys[rg * 8 + i], key);
  }
  __syncthreads();

  // finalize: gather z_q, write index, accumulate min distance (= d_min)
  float dmin = 0.f;
  {
    const int r = t >> 1, h = t & 1;
    u64 key = s.keys[r];
    int idx = (int)(u32)key;
    const float4* src = (const float4*)(emb + (size_t)idx * D + h * 32);
    float4* dst = (float4*)(out_zq + (size_t)(rowBase + r) * D + h * 32);
    #pragma unroll
    for (int i = 0; i < 8; i++) dst[i] = src[i];
    if (h == 0) {
      out_idx[rowBase + r] = (float)idx;
      dmin = funkey((u32)(key >> 32));   // d_min = ||z - e_idx||^2 (quantized)
    }
  }

  // deterministic per-block loss partial
  #pragma unroll
  for (int o = 16; o > 0; o >>= 1) dmin += __shfl_xor_sync(0xFFFFFFFFu, dmin, o);
  if ((t & 31) == 0) s.red[t >> 5] = dmin;
  __syncthreads();
  if (t == 0) {
    float tot = 0.f;
    #pragma unroll
    for (int i = 0; i < 8; i++) tot += s.red[i];
    g_partial[blockIdx.x] = tot;
  }
}

// ---------------------------------------------------------------------------
// Kernel 2: deterministic loss reduction (double accumulation)
// loss = (1 + BETA) * mean(||z - e||^2) = 1.25 * sum(d_min) / (N*D)
// ---------------------------------------------------------------------------
__global__ void vq_finish_kernel(float* __restrict__ out_loss, int nb, long long nd) {
  int t = threadIdx.x;
  double v = (t < nb) ? (double)g_partial[t] : 0.0;
  #pragma unroll
  for (int o = 16; o > 0; o >>= 1) v += __shfl_xor_sync(0xFFFFFFFFu, v, o);
  __shared__ double red[32];
  if ((t & 31) == 0) red[t >> 5] = v;
  __syncthreads();
  if (t < 32) {
    double w = (t < (int)(blockDim.x >> 5)) ? red[t] : 0.0;
    #pragma unroll
    for (int o = 16; o > 0; o >>= 1) w += __shfl_xor_sync(0xFFFFFFFFu, w, o);
    if (t == 0) out_loss[0] = (float)(1.25 * w / (double)nd);
  }
}

// ---------------------------------------------------------------------------
extern "C" void kernel_launch(void* const* d_in, const int* in_sizes, int n_in,
                              void* d_out, int out_size) {
  const float* z   = (const float*)d_in[0];   // [N,1,64] fp32
  const float* emb = (const float*)d_in[1];   // [1024,64] fp32
  float* out = (float*)d_out;

  const int N = in_sizes[0] / D;              // 131072
  float* out_zq   = out;                      // [N*D]
  float* out_idx  = out + (size_t)N * D;      // [N] (indices as float)
  float* out_loss = out_idx + N;              // [1]

  vq_en_kernel<<<(KCODES + 255) / 256, 256>>>(emb);

  int smem = (int)sizeof(Smem);
  cudaFuncSetAttribute(vq_main_kernel,
                       cudaFuncAttributeMaxDynamicSharedMemorySize, smem);
  vq_main_kernel<<<N / TM, THREADS, smem>>>(z, emb, out_zq, out_idx);

  vq_finish_kernel<<<1, 1024>>>(out_loss, N / TM, (long long)N * D);
}

// round 5
// speedup vs baseline: 2.2506x; 2.2506x over previous
#include <cuda_runtime.h>
#include <cfloat>

// Problem constants (fixed by the dataset)
#define D        64
#define KCODES   1024
#define TM       128   // rows per block
#define TK       128   // codes per smem chunk
#define THREADS  256

// zn summation-order emulation: XLA AddReduce shuffle-halving, 4 lanes,
// (S0+S2)+(S1+S3)  [verified passing in round 4]
typedef unsigned long long u64;
typedef unsigned int       u32;

// Scratch (allocation-free rule: __device__ globals)
__device__ float g_en[KCODES];        // ||e_k||^2, reference-order fp32
__device__ float g_partial[1024];     // per-block sum of min distances

struct Smem {
  float zs[D][TM];        // z tile, d-major (transposed)          32 KB
  float es[D][TK];        // e chunk, d-major, INTERLEAVED:        32 KB
                          //   es[d][j*16+cg] = e_{cg*8+j}[d]
  float ens[TK];          // ||e||^2 for chunk
  u64   keys[TM];         // packed (orderable(d)<<32)|index
  float zn[TM];           // ||z_row||^2, reference-order fp32
  float red[8];           // loss warp partials
};

__device__ __forceinline__ u32 fkey(float f) {
  u32 u = __float_as_uint(f);
  return (u & 0x80000000u) ? ~u : (u | 0x80000000u);
}
__device__ __forceinline__ float funkey(u32 u) {
  u32 v = (u & 0x80000000u) ? (u & 0x7FFFFFFFu) : ~u;
  return __uint_as_float(v);
}
__device__ __forceinline__ u64 pack2(float f) {
  u64 r; u32 b = __float_as_uint(f);
  asm("mov.b64 %0, {%1, %1};" : "=l"(r) : "r"(b));
  return r;
}
__device__ __forceinline__ void ffma2(u64& acc, u64 a, u64 b) {
  asm("fma.rn.f32x2 %0, %1, %2, %0;" : "+l"(acc) : "l"(a), "l"(b));
}

// Reference-order squared-norm of 64 values at (base, stride):
// XLA:CPU fp32 reduce — 4 lanes, horizontal (S0+S2)+(S1+S3).
__device__ __forceinline__ float ref_sqnorm(const float* base, int stride) {
  float S[4] = {0.f, 0.f, 0.f, 0.f};
  #pragma unroll
  for (int i = 0; i < D / 4; i++) {
    #pragma unroll
    for (int j = 0; j < 4; j++) {
      float v = base[(4 * i + j) * stride];
      S[j] = __fadd_rn(S[j], __fmul_rn(v, v));
    }
  }
  return __fadd_rn(__fadd_rn(S[0], S[2]), __fadd_rn(S[1], S[3]));
}

// ---------------------------------------------------------------------------
// Kernel 0: codebook norms ||e_k||^2 (reference fp32 order)
// ---------------------------------------------------------------------------
__global__ void vq_en_kernel(const float* __restrict__ emb) {
  int k = blockIdx.x * blockDim.x + threadIdx.x;
  if (k < KCODES)
    g_en[k] = ref_sqnorm(emb + (size_t)k * D, 1);
}

// ---------------------------------------------------------------------------
// Kernel 1: scores + quantized argmin (reference numerics) + gather + loss
// ---------------------------------------------------------------------------
__global__ void __launch_bounds__(THREADS, 2)
vq_main_kernel(const float* __restrict__ z, const float* __restrict__ emb,
               float* __restrict__ out_zq, float* __restrict__ out_idx) {
  extern __shared__ __align__(16) unsigned char smem_raw[];
  Smem& s = *reinterpret_cast<Smem*>(smem_raw);
  const int t = threadIdx.x;
  const int rowBase = blockIdx.x * TM;

  for (int i = t; i < TM; i += THREADS) s.keys[i] = ~0ULL;

  // Load z tile transposed. 2 threads per row, each loads half as 8x float4.
  {
    const int r = t >> 1, h = t & 1;
    const float4* zr = (const float4*)(z + (size_t)(rowBase + r) * D + h * 32);
    #pragma unroll
    for (int i = 0; i < 8; i++) {
      float4 v = zr[i];
      int d0 = h * 32 + i * 4;
      s.zs[d0 + 0][r] = v.x; s.zs[d0 + 1][r] = v.y;
      s.zs[d0 + 2][r] = v.z; s.zs[d0 + 3][r] = v.w;
    }
  }
  __syncthreads();

  // ||z_row||^2 in the reference's exact fp32 summation order.
  if (t < TM)
    s.zn[t] = ref_sqnorm(&s.zs[0][t], TM);
  __syncthreads();

  const int cg = t & 15;   // col group: 8 codes (strided by 16 in smem)
  const int rg = t >> 4;   // row group: 8 rows (4 f32x2 pairs)

  float znr[8];
  #pragma unroll
  for (int i = 0; i < 8; i++) znr[i] = s.zn[rg * 8 + i];

  float minv[8];
  int   mini[8];
  #pragma unroll
  for (int i = 0; i < 8; i++) { minv[i] = FLT_MAX; mini[i] = 0; }

  for (int kc = 0; kc < KCODES; kc += TK) {
    __syncthreads();   // prior chunk's reads done before overwrite
    {
      // loader: code r = t>>1, half h = t&1; interleaved scatter:
      // es[d][(r&7)*16 + (r>>3)] = e_r[d]
      const int r = t >> 1, h = t & 1;
      const int pos = (r & 7) * 16 + (r >> 3);
      const float4* er = (const float4*)(emb + (size_t)(kc + r) * D + h * 32);
      #pragma unroll
      for (int i = 0; i < 8; i++) {
        float4 v = er[i];
        int d0 = h * 32 + i * 4;
        s.es[d0 + 0][pos] = v.x; s.es[d0 + 1][pos] = v.y;
        s.es[d0 + 2][pos] = v.z; s.es[d0 + 3][pos] = v.w;
      }
      if (t < TK) s.ens[t] = g_en[kc + t];
    }
    __syncthreads();

    // 8 rows (4 f32x2 pairs) x 8 codes per thread.
    u64 acc[4][8];
    #pragma unroll
    for (int i = 0; i < 4; i++)
      #pragma unroll
      for (int j = 0; j < 8; j++) acc[i][j] = 0ULL;

    #pragma unroll 4
    for (int d = 0; d < D; d++) {
      u64 za[4];
      #pragma unroll
      for (int i = 0; i < 4; i++)
        za[i] = *(const u64*)&s.zs[d][rg * 8 + 2 * i];
      #pragma unroll
      for (int j = 0; j < 8; j++) {
        u64 e2 = pack2(s.es[d][j * 16 + cg]);   // conflict-free broadcast LDS.32
        ffma2(acc[0][j], za[0], e2);
        ffma2(acc[1][j], za[1], e2);
        ffma2(acc[2][j], za[2], e2);
        ffma2(acc[3][j], za[3], e2);
      }
    }

    // Reference numerics: d = fl(fl(zn + en) - 2*dot). Quantized argmin,
    // strict < keeps first (lowest) index within the thread's ascending cols.
    #pragma unroll
    for (int j = 0; j < 8; j++) {
      const int col = kc + cg * 8 + j;
      const float en = s.ens[cg * 8 + j];
      #pragma unroll
      for (int i = 0; i < 4; i++) {
        u64 a = acc[i][j];
        float lo = __uint_as_float((u32)a);
        float hi = __uint_as_float((u32)(a >> 32));
        float d0 = __fsub_rn(__fadd_rn(znr[2 * i],     en), __fadd_rn(lo, lo));
        float d1 = __fsub_rn(__fadd_rn(znr[2 * i + 1], en), __fadd_rn(hi, hi));
        if (d0 < minv[2 * i])     { minv[2 * i]     = d0; mini[2 * i]     = col; }
        if (d1 < minv[2 * i + 1]) { minv[2 * i + 1] = d1; mini[2 * i + 1] = col; }
      }
    }
  }

  // cross-thread argmin: packed key min picks min d, tie -> lowest index
  #pragma unroll
  for (int i = 0; i < 8; i++) {
    u64 key = ((u64)fkey(minv[i]) << 32) | (u32)mini[i];
    atomicMin(&s.keys[rg * 8 + i], key);
  }
  __syncthreads();

  // finalize: gather z_q, write index, accumulate min distance (= d_min)
  float dmin = 0.f;
  {
    const int r = t >> 1, h = t & 1;
    u64 key = s.keys[r];
    int idx = (int)(u32)key;
    const float4* src = (const float4*)(emb + (size_t)idx * D + h * 32);
    float4* dst = (float4*)(out_zq + (size_t)(rowBase + r) * D + h * 32);
    #pragma unroll
    for (int i = 0; i < 8; i++) dst[i] = src[i];
    if (h == 0) {
      out_idx[rowBase + r] = (float)idx;
      dmin = funkey((u32)(key >> 32));   // d_min = ||z - e_idx||^2 (quantized)
    }
  }

  // deterministic per-block loss partial
  #pragma unroll
  for (int o = 16; o > 0; o >>= 1) dmin += __shfl_xor_sync(0xFFFFFFFFu, dmin, o);
  if ((t & 31) == 0) s.red[t >> 5] = dmin;
  __syncthreads();
  if (t == 0) {
    float tot = 0.f;
    #pragma unroll
    for (int i = 0; i < 8; i++) tot += s.red[i];
    g_partial[blockIdx.x] = tot;
  }
}

// ---------------------------------------------------------------------------
// Kernel 2: deterministic loss reduction (double accumulation)
// loss = (1 + BETA) * mean(||z - e||^2) = 1.25 * sum(d_min) / (N*D)
// ---------------------------------------------------------------------------
__global__ void vq_finish_kernel(float* __restrict__ out_loss, int nb, long long nd) {
  int t = threadIdx.x;
  double v = (t < nb) ? (double)g_partial[t] : 0.0;
  #pragma unroll
  for (int o = 16; o > 0; o >>= 1) v += __shfl_xor_sync(0xFFFFFFFFu, v, o);
  __shared__ double red[32];
  if ((t & 31) == 0) red[t >> 5] = v;
  __syncthreads();
  if (t < 32) {
    double w = (t < (int)(blockDim.x >> 5)) ? red[t] : 0.0;
    #pragma unroll
    for (int o = 16; o > 0; o >>= 1) w += __shfl_xor_sync(0xFFFFFFFFu, w, o);
    if (t == 0) out_loss[0] = (float)(1.25 * w / (double)nd);
  }
}

// ---------------------------------------------------------------------------
extern "C" void kernel_launch(void* const* d_in, const int* in_sizes, int n_in,
                              void* d_out, int out_size) {
  const float* z   = (const float*)d_in[0];   // [N,1,64] fp32
  const float* emb = (const float*)d_in[1];   // [1024,64] fp32
  float* out = (float*)d_out;

  const int N = in_sizes[0] / D;              // 131072
  float* out_zq   = out;                      // [N*D]
  float* out_idx  = out + (size_t)N * D;      // [N] (indices as float)
  float* out_loss = out_idx + N;              // [1]

  vq_en_kernel<<<(KCODES + 255) / 256, 256>>>(emb);

  int smem = (int)sizeof(Smem);
  cudaFuncSetAttribute(vq_main_kernel,
                       cudaFuncAttributeMaxDynamicSharedMemorySize, smem);
  vq_main_kernel<<<N / TM, THREADS, smem>>>(z, emb, out_zq, out_idx);

  vq_finish_kernel<<<1, 1024>>>(out_loss, N / TM, (long long)N * D);
}